// round 1
// baseline (speedup 1.0000x reference)
#include <cuda_runtime.h>
#include <cuda_bf16.h>

// ---------------------------------------------------------------------------
// LeafOnlyNet fused block-attention kernel.
// B=4, NB=256, L=64, H=8, C=128, D=16, EG_HID=16. 1024 blocks of 64 tokens.
// One CTA per (b, nb) block, 256 threads, everything fused in SMEM.
// ---------------------------------------------------------------------------

#define QS 388              // qkv smem row stride (floats): 16B aligned, bank-skewed
#define OFF_LB   0          // lb[k][q]            : 64*64 floats        = 4096
#define OFF_EG   4096       // eg[h][k][q] bf16    : 8*64*64 bf16        = 16384 floats
#define OFF_QKV  20480      // qkv[64][388] floats : 24832
#define OFF_TR   45312      // transient region (Xs+Wc / Outs+Wp / phase1 weights)
#define OFF_XS   OFF_TR                    // Xs[64][128]   = 8192 floats
#define OFF_WC   (OFF_TR + 8192)           // Wc[8][384]    = 3072 floats
#define OFF_OUTS OFF_TR                    // Outs[64][129] = 8256 floats
#define OFF_WP   (OFF_TR + 8256)           // Wp[16][128]   = 2048 floats
#define OFF_NEED 56576                     // need[64]
#define SMEM_FLOATS 56640
#define SMEM_BYTES  (SMEM_FLOATS * 4)      // 226560 bytes

static __device__ __align__(16) float g_qkv_wt[128 * 384];   // Wt[k][c] = qkv_w[c][k]
static __device__ __align__(16) float g_proj_wt[128 * 128];  // Wt[k][c] = proj_w[c][k]

__global__ void k_transpose_qkv(const float* __restrict__ w) {
    int idx = blockIdx.x * 256 + threadIdx.x;
    if (idx < 128 * 384) {
        int k = idx / 384, c = idx % 384;
        g_qkv_wt[idx] = w[c * 128 + k];
    }
}

__global__ void k_transpose_proj(const float* __restrict__ w) {
    int idx = blockIdx.x * 256 + threadIdx.x;
    if (idx < 128 * 128) {
        int k = idx / 128, c = idx % 128;
        g_proj_wt[idx] = w[c * 128 + k];
    }
}

__global__ void __launch_bounds__(256, 1)
fused_attn(const float* __restrict__ x,
           const int*   __restrict__ attn_mask,
           const float* __restrict__ ef,
           const float* __restrict__ qkv_b,
           const float* __restrict__ proj_b,
           const float* __restrict__ eg_w1,
           const float* __restrict__ eg_b1,
           const float* __restrict__ eg_w2,
           const float* __restrict__ eg_b2,
           float* __restrict__ out)
{
    extern __shared__ float sm[];
    float*          lb   = sm + OFF_LB;
    __nv_bfloat16*  egs  = (__nv_bfloat16*)(sm + OFF_EG);
    float*          qkv  = sm + OFF_QKV;
    float*          need = sm + OFF_NEED;

    const int tid  = threadIdx.x;
    const int blk  = blockIdx.x;
    const long long row0 = (long long)blk * 64;
    const int*   am  = attn_mask + (long long)blk * 4096;
    const float* efb = ef        + (long long)blk * 16384;

    // ---------------- phase 0: "need" = row has no neighbors ----------------
    if (tid < 64) {
        int s = 0;
        const int* r = am + tid * 64;
#pragma unroll 16
        for (int j = 0; j < 64; j++) s += r[j];
        need[tid] = (s < 1) ? 1.0f : 0.0f;
    }

    // stage edge-MLP weights into smem (transient region, freed before X load)
    float* wsm = sm + OFF_TR;   // [0,64)=w1, [64,80)=b1, [80,88)=b2, [88,216)=w2
    if (tid < 64)  wsm[tid]       = eg_w1[tid];
    if (tid < 16)  wsm[64 + tid]  = eg_b1[tid];
    if (tid < 8)   wsm[80 + tid]  = eg_b2[tid];
    if (tid < 128) wsm[88 + tid]  = eg_w2[tid];
    __syncthreads();

    // ---------------- phase 1: edge-gate MLP + logit bias + mask ------------
    {
        float rw2[128];
#pragma unroll
        for (int i = 0; i < 128; i++) rw2[i] = wsm[88 + i];

        const float4* ef4 = (const float4*)efb;
        for (int t = 0; t < 16; t++) {
            int idx = t * 256 + tid;
            int q = idx >> 6, k = idx & 63;
            float4 e = ef4[idx];
            float m = (float)am[idx];
            if (q == k) {
                e.x = 0.f; e.y = 0.f; e.z = 0.f; e.w = 1.f;
                m = fmaxf(m, need[q]);
            }
            float acc[8];
#pragma unroll
            for (int h = 0; h < 8; h++) acc[h] = wsm[80 + h];
#pragma unroll
            for (int j = 0; j < 16; j++) {
                float pre = wsm[j * 4 + 0] * e.x + wsm[j * 4 + 1] * e.y +
                            wsm[j * 4 + 2] * e.z + wsm[j * 4 + 3] * e.w + wsm[64 + j];
                float g = 0.5f * pre * (1.0f + erff(pre * 0.70710678118654752f));
#pragma unroll
                for (int h = 0; h < 8; h++) acc[h] = fmaf(g, rw2[h * 16 + j], acc[h]);
            }
            bool on = (m > 0.0f);
            lb[k * 64 + q] = on ? e.w : -1e9f;
#pragma unroll
            for (int h = 0; h < 8; h++)
                egs[h * 4096 + k * 64 + q] = __float2bfloat16(on ? acc[h] : 0.0f);
        }
    }
    __syncthreads();

    // ---------------- phase 2: load X, QKV GEMM (64x384 = X @ Wt) -----------
    {
        float4* xs4 = (float4*)(sm + OFF_XS);
        const float4* xg4 = (const float4*)(x + row0 * 128);
#pragma unroll
        for (int i = 0; i < 8; i++) xs4[i * 256 + tid] = xg4[i * 256 + tid];
    }
    __syncthreads();

    const int tr = tid >> 5;   // 0..7  (warp id)
    const int tc = tid & 31;   // 0..31 (lane)

    {
        float acc[8][12];
#pragma unroll
        for (int i = 0; i < 8; i++)
#pragma unroll
            for (int j = 0; j < 12; j++) acc[i][j] = 0.0f;

        float* xsf = sm + OFF_XS;
        float* wc  = sm + OFF_WC;
        for (int c = 0; c < 16; c++) {          // K chunks of 8
            __syncthreads();
            const float4* src = (const float4*)(g_qkv_wt + c * 8 * 384);
            float4* dst = (float4*)wc;
#pragma unroll
            for (int i = 0; i < 3; i++) dst[i * 256 + tid] = src[i * 256 + tid];
            __syncthreads();
#pragma unroll
            for (int kk = 0; kk < 8; kk++) {
                float xv[8];
#pragma unroll
                for (int i = 0; i < 8; i++)
                    xv[i] = xsf[(tr * 8 + i) * 128 + c * 8 + kk];
#pragma unroll
                for (int j = 0; j < 12; j++) {
                    float wv = wc[kk * 384 + tc + 32 * j];
#pragma unroll
                    for (int i = 0; i < 8; i++)
                        acc[i][j] = fmaf(xv[i], wv, acc[i][j]);
                }
            }
        }
        // write qkv (+bias) to padded smem
#pragma unroll
        for (int j = 0; j < 12; j++) {
            int col = tc + 32 * j;
            float bv = __ldg(qkv_b + col);
#pragma unroll
            for (int i = 0; i < 8; i++)
                qkv[(tr * 8 + i) * QS + col] = acc[i][j] + bv;
        }
    }
    __syncthreads();

    // ---------------- phase 3: attention (warp h, 2 q-rows per lane) --------
    {
        const int h = tr;
        const int lane = tc;
        const float scale = 0.25f;   // D^-0.5, D=16

        float qr[2][16];
#pragma unroll
        for (int r = 0; r < 2; r++) {
            const float4* qp = (const float4*)(qkv + (lane + 32 * r) * QS + h * 16);
#pragma unroll
            for (int d4 = 0; d4 < 4; d4++) {
                float4 v = qp[d4];
                qr[r][d4 * 4 + 0] = v.x; qr[r][d4 * 4 + 1] = v.y;
                qr[r][d4 * 4 + 2] = v.z; qr[r][d4 * 4 + 3] = v.w;
            }
        }

        float mrun[2] = {-3e38f, -3e38f};
        float lrun[2] = {0.0f, 0.0f};
        float o[2][16];
#pragma unroll
        for (int r = 0; r < 2; r++)
#pragma unroll
            for (int d = 0; d < 16; d++) o[r][d] = 0.0f;

        const __nv_bfloat16* egh = egs + h * 4096;

        for (int c = 0; c < 4; c++) {           // 4 chunks of 16 keys
            float s[2][16];
#pragma unroll
            for (int kk = 0; kk < 16; kk++) {
                int k = c * 16 + kk;
                const float4* kp = (const float4*)(qkv + k * QS + 128 + h * 16);
                float kvv[16];
#pragma unroll
                for (int d4 = 0; d4 < 4; d4++) {
                    float4 v = kp[d4];
                    kvv[d4 * 4 + 0] = v.x; kvv[d4 * 4 + 1] = v.y;
                    kvv[d4 * 4 + 2] = v.z; kvv[d4 * 4 + 3] = v.w;
                }
                float d0 = 0.0f, d1 = 0.0f;
#pragma unroll
                for (int d = 0; d < 16; d++) {
                    d0 = fmaf(qr[0][d], kvv[d], d0);
                    d1 = fmaf(qr[1][d], kvv[d], d1);
                }
                float lb0 = lb[k * 64 + lane];
                float lb1 = lb[k * 64 + lane + 32];
                float e0 = __bfloat162float(egh[k * 64 + lane]);
                float e1 = __bfloat162float(egh[k * 64 + lane + 32]);
                s[0][kk] = fmaf(d0, scale, lb0) + e0;
                s[1][kk] = fmaf(d1, scale, lb1) + e1;
            }
            // online softmax update
#pragma unroll
            for (int r = 0; r < 2; r++) {
                float ml = s[r][0];
#pragma unroll
                for (int kk = 1; kk < 16; kk++) ml = fmaxf(ml, s[r][kk]);
                float mnew = fmaxf(mrun[r], ml);
                float corr = __expf(mrun[r] - mnew);
                mrun[r] = mnew;
                lrun[r] *= corr;
#pragma unroll
                for (int d = 0; d < 16; d++) o[r][d] *= corr;
#pragma unroll
                for (int kk = 0; kk < 16; kk++) {
                    float p = __expf(s[r][kk] - mnew);
                    lrun[r] += p;
                    s[r][kk] = p;
                }
            }
            // accumulate P @ V for this chunk
#pragma unroll
            for (int kk = 0; kk < 16; kk++) {
                int k = c * 16 + kk;
                const float4* vp = (const float4*)(qkv + k * QS + 256 + h * 16);
                float p0 = s[0][kk], p1 = s[1][kk];
#pragma unroll
                for (int d4 = 0; d4 < 4; d4++) {
                    float4 v = vp[d4];
                    o[0][d4 * 4 + 0] = fmaf(p0, v.x, o[0][d4 * 4 + 0]);
                    o[0][d4 * 4 + 1] = fmaf(p0, v.y, o[0][d4 * 4 + 1]);
                    o[0][d4 * 4 + 2] = fmaf(p0, v.z, o[0][d4 * 4 + 2]);
                    o[0][d4 * 4 + 3] = fmaf(p0, v.w, o[0][d4 * 4 + 3]);
                    o[1][d4 * 4 + 0] = fmaf(p1, v.x, o[1][d4 * 4 + 0]);
                    o[1][d4 * 4 + 1] = fmaf(p1, v.y, o[1][d4 * 4 + 1]);
                    o[1][d4 * 4 + 2] = fmaf(p1, v.z, o[1][d4 * 4 + 2]);
                    o[1][d4 * 4 + 3] = fmaf(p1, v.w, o[1][d4 * 4 + 3]);
                }
            }
        }

        float* outs = sm + OFF_OUTS;
#pragma unroll
        for (int r = 0; r < 2; r++) {
            float inv = 1.0f / lrun[r];
#pragma unroll
            for (int d = 0; d < 16; d++)
                outs[(lane + 32 * r) * 129 + h * 16 + d] = o[r][d] * inv;
        }
    }
    __syncthreads();

    // ---------------- phase 4: output projection (64x128 = Outs @ Wt2) ------
    {
        float pacc[8][4];
#pragma unroll
        for (int i = 0; i < 8; i++)
#pragma unroll
            for (int j = 0; j < 4; j++) pacc[i][j] = 0.0f;

        float* outs = sm + OFF_OUTS;
        float* wp   = sm + OFF_WP;
        for (int c = 0; c < 8; c++) {           // K chunks of 16
            __syncthreads();
            const float4* src = (const float4*)(g_proj_wt + c * 16 * 128);
            float4* dst = (float4*)wp;
#pragma unroll
            for (int i = 0; i < 2; i++) dst[i * 256 + tid] = src[i * 256 + tid];
            __syncthreads();
#pragma unroll
            for (int kk = 0; kk < 16; kk++) {
                float ov[8];
#pragma unroll
                for (int i = 0; i < 8; i++)
                    ov[i] = outs[(tr * 8 + i) * 129 + c * 16 + kk];
#pragma unroll
                for (int j = 0; j < 4; j++) {
                    float wv = wp[kk * 128 + tc + 32 * j];
#pragma unroll
                    for (int i = 0; i < 8; i++)
                        pacc[i][j] = fmaf(ov[i], wv, pacc[i][j]);
                }
            }
        }

        float* og = out + row0 * 128;
#pragma unroll
        for (int j = 0; j < 4; j++) {
            int col = tc + 32 * j;
            float bv = __ldg(proj_b + col);
#pragma unroll
            for (int i = 0; i < 8; i++)
                og[(tr * 8 + i) * 128 + col] = pacc[i][j] + bv;
        }
    }
}

extern "C" void kernel_launch(void* const* d_in, const int* in_sizes, int n_in,
                              void* d_out, int out_size)
{
    (void)in_sizes; (void)n_in; (void)out_size;
    const float* x      = (const float*)d_in[0];
    const int*   am     = (const int*)  d_in[1];
    const float* ef     = (const float*)d_in[2];
    const float* qkv_w  = (const float*)d_in[3];
    const float* qkv_b  = (const float*)d_in[4];
    const float* proj_w = (const float*)d_in[5];
    const float* proj_b = (const float*)d_in[6];
    const float* eg_w1  = (const float*)d_in[7];
    const float* eg_b1  = (const float*)d_in[8];
    const float* eg_w2  = (const float*)d_in[9];
    const float* eg_b2  = (const float*)d_in[10];
    float* out = (float*)d_out;

    k_transpose_qkv<<<192, 256>>>(qkv_w);
    k_transpose_proj<<<64, 256>>>(proj_w);

    cudaFuncSetAttribute(fused_attn,
                         cudaFuncAttributeMaxDynamicSharedMemorySize, SMEM_BYTES);
    fused_attn<<<1024, 256, SMEM_BYTES>>>(x, am, ef, qkv_b, proj_b,
                                          eg_w1, eg_b1, eg_w2, eg_b2, out);
}

// round 2
// speedup vs baseline: 2.0689x; 2.0689x over previous
#include <cuda_runtime.h>
#include <cuda_bf16.h>

// ---------------------------------------------------------------------------
// LeafOnlyNet fused block-attention kernel, round 2: tf32 mma.sync GEMMs.
// B=4, NB=256, L=64, H=8, C=128, D=16. One CTA per (b,nb) block, 256 threads.
// ---------------------------------------------------------------------------

#define QS 388              // qkv smem row stride (floats)
#define OFF_LB   0          // lb[k][q^]           : 64*64             = 4096
#define OFF_EG   4096       // eg[h][k][q^] bf16   : 8*64*64 bf16      = 16384 floats
#define OFF_QKV  20480      // qkv[64][388]        : 24832
#define OFF_TR   45312      // transient: Xs[64][132]+Wc[8][388] / Outs[64][132]+Wp[16][132]
#define OFF_XS   OFF_TR
#define OFF_WC   (OFF_TR + 8448)
#define OFF_OUTS OFF_TR
#define OFF_WP   (OFF_TR + 8448)
#define OFF_NEED 56864
#define OFF_QB   56928      // qkv_b staged (384)
#define OFF_PB   57312      // proj_b staged (128)
#define SMEM_FLOATS 57440
#define SMEM_BYTES  (SMEM_FLOATS * 4)   // 229760 B

static __device__ __align__(16) float g_qkv_wt[128 * 384];   // Wt[k][c] = qkv_w[c][k]
static __device__ __align__(16) float g_proj_wt[128 * 128];  // Wt[k][c] = proj_w[c][k]

__global__ void k_transpose_qkv(const float* __restrict__ w) {
    int idx = blockIdx.x * 256 + threadIdx.x;
    if (idx < 128 * 384) {
        int k = idx / 384, c = idx % 384;
        g_qkv_wt[idx] = w[c * 128 + k];
    }
}
__global__ void k_transpose_proj(const float* __restrict__ w) {
    int idx = blockIdx.x * 256 + threadIdx.x;
    if (idx < 128 * 128) {
        int k = idx / 128, c = idx % 128;
        g_proj_wt[idx] = w[c * 128 + k];
    }
}

__device__ __forceinline__ unsigned f2tf(float f) {
    unsigned u;
    asm("cvt.rna.tf32.f32 %0, %1;" : "=r"(u) : "f"(f));
    return u;
}

__device__ __forceinline__ void mma8(float* d, const unsigned* a, unsigned b0, unsigned b1) {
    asm volatile(
        "mma.sync.aligned.m16n8k8.row.col.f32.tf32.tf32.f32 "
        "{%0,%1,%2,%3},{%4,%5,%6,%7},{%8,%9},{%0,%1,%2,%3};\n"
        : "+f"(d[0]), "+f"(d[1]), "+f"(d[2]), "+f"(d[3])
        : "r"(a[0]), "r"(a[1]), "r"(a[2]), "r"(a[3]), "r"(b0), "r"(b1));
}

__global__ void __launch_bounds__(256, 1)
fused_attn(const float* __restrict__ x,
           const int*   __restrict__ attn_mask,
           const float* __restrict__ ef,
           const float* __restrict__ qkv_b,
           const float* __restrict__ proj_b,
           const float* __restrict__ eg_w1,
           const float* __restrict__ eg_b1,
           const float* __restrict__ eg_w2,
           const float* __restrict__ eg_b2,
           float* __restrict__ out)
{
    extern __shared__ float sm[];
    float*          lb   = sm + OFF_LB;
    __nv_bfloat16*  egs  = (__nv_bfloat16*)(sm + OFF_EG);
    float*          qkv  = sm + OFF_QKV;
    float*          need = sm + OFF_NEED;
    float*          qb   = sm + OFF_QB;
    float*          pb   = sm + OFF_PB;

    const int tid  = threadIdx.x;
    const int blk  = blockIdx.x;
    const int tr   = tid >> 5;     // warp id
    const int lane = tid & 31;
    const int g    = lane >> 2;    // mma group row
    const int q4   = lane & 3;     // mma group col
    const long long row0 = (long long)blk * 64;
    const int*   am  = attn_mask + (long long)blk * 4096;
    const float* efb = ef        + (long long)blk * 16384;

    // ---------------- phase 0: need[] + stage biases + edge-MLP weights -----
    {
        int row = tid >> 2, qt = tid & 3;
        const int4* r4 = (const int4*)(am + row * 64 + qt * 16);
        int s = 0;
#pragma unroll
        for (int i = 0; i < 4; i++) { int4 v = r4[i]; s += v.x + v.y + v.z + v.w; }
        s += __shfl_xor_sync(0xffffffffu, s, 1);
        s += __shfl_xor_sync(0xffffffffu, s, 2);
        if (qt == 0) need[row] = (s < 1) ? 1.0f : 0.0f;
    }
    for (int i = tid; i < 384; i += 256) qb[i] = qkv_b[i];
    if (tid < 128) pb[tid] = proj_b[tid];

    // edge-MLP weights: [0,64)=w1[j][4], [64,80)=b1, [80,88)=b2, [88,216)=w2t[j][8]
    float* wsm = sm + OFF_TR;
    if (tid < 64)  wsm[tid]      = eg_w1[tid];
    if (tid < 16)  wsm[64 + tid] = eg_b1[tid];
    if (tid < 8)   wsm[80 + tid] = eg_b2[tid];
    if (tid < 128) wsm[88 + tid] = eg_w2[(tid & 7) * 16 + (tid >> 3)];
    __syncthreads();

    // ---------------- phase 1: edge-gate MLP + logit bias + mask ------------
    {
        float b2r[8];
#pragma unroll
        for (int h = 0; h < 8; h++) b2r[h] = wsm[80 + h];

        const float4* ef4 = (const float4*)efb;
        for (int ch = 0; ch < 4; ch++) {
            float4 e[4]; float on[4]; int ki[4], qi[4];
#pragma unroll
            for (int p = 0; p < 4; p++) {
                int idx = (ch * 4 + p) * 256 + tid;
                int q = idx >> 6, k = idx & 63;
                float4 ev = ef4[idx];
                float m = (float)am[idx];
                if (q == k) { ev.x = 0.f; ev.y = 0.f; ev.z = 0.f; ev.w = 1.f;
                              m = fmaxf(m, need[q]); }
                e[p] = ev; on[p] = (m > 0.0f) ? 1.0f : 0.0f; qi[p] = q; ki[p] = k;
            }
            float acc[4][8];
#pragma unroll
            for (int p = 0; p < 4; p++)
#pragma unroll
                for (int h = 0; h < 8; h++) acc[p][h] = b2r[h];
#pragma unroll
            for (int j = 0; j < 16; j++) {
                float4 w  = *(const float4*)(wsm + j * 4);
                float  b  = wsm[64 + j];
                float4 wa = *(const float4*)(wsm + 88 + j * 8);
                float4 wb = *(const float4*)(wsm + 88 + j * 8 + 4);
#pragma unroll
                for (int p = 0; p < 4; p++) {
                    float pre = fmaf(w.x, e[p].x, fmaf(w.y, e[p].y,
                                fmaf(w.z, e[p].z, fmaf(w.w, e[p].w, b))));
                    // gelu(x) = 0.5 x (1 + erf(x/sqrt2)); erf via odd Taylor deg-9
                    float y = 0.70710678118654752f * pre;
                    float t = y * y;
                    float er = y * fmaf(t, fmaf(t, fmaf(t, fmaf(t,
                               0.00522397762544218f, -0.02686617064513125f),
                               0.11283791670955126f), -0.37612638903183752f),
                               1.12837916709551257f);
                    float gl = 0.5f * pre * (1.0f + er);
                    acc[p][0] = fmaf(gl, wa.x, acc[p][0]);
                    acc[p][1] = fmaf(gl, wa.y, acc[p][1]);
                    acc[p][2] = fmaf(gl, wa.z, acc[p][2]);
                    acc[p][3] = fmaf(gl, wa.w, acc[p][3]);
                    acc[p][4] = fmaf(gl, wb.x, acc[p][4]);
                    acc[p][5] = fmaf(gl, wb.y, acc[p][5]);
                    acc[p][6] = fmaf(gl, wb.z, acc[p][6]);
                    acc[p][7] = fmaf(gl, wb.w, acc[p][7]);
                }
            }
#pragma unroll
            for (int p = 0; p < 4; p++) {
                int q = qi[p], k = ki[p];
                int base = k * 64 + (q ^ (k & 31));   // XOR swizzle: conflict-free
                bool o = on[p] > 0.0f;
                lb[base] = o ? e[p].w : -1e9f;
#pragma unroll
                for (int h = 0; h < 8; h++)
                    egs[h * 4096 + base] = __float2bfloat16(o ? acc[p][h] : 0.0f);
            }
        }
    }
    __syncthreads();

    // ---------------- phase 2: load X (tf32), QKV via mma -------------------
    {
        float* xs = sm + OFF_XS;
        const float4* xg4 = (const float4*)(x + row0 * 128);
#pragma unroll
        for (int i = 0; i < 8; i++) {
            int idx = i * 256 + tid;
            float4 v = xg4[idx];
            int r = idx >> 5, c4 = idx & 31;
            float4 w;
            w.x = __uint_as_float(f2tf(v.x)); w.y = __uint_as_float(f2tf(v.y));
            w.z = __uint_as_float(f2tf(v.z)); w.w = __uint_as_float(f2tf(v.w));
            *(float4*)(xs + r * 132 + c4 * 4) = w;
        }
    }

    {
        float acc[4][6][4];
#pragma unroll
        for (int mt = 0; mt < 4; mt++)
#pragma unroll
            for (int nt = 0; nt < 6; nt++)
#pragma unroll
                for (int i = 0; i < 4; i++) acc[mt][nt][i] = 0.0f;

        const int nb0 = tr * 48;
        float* xs = sm + OFF_XS;
        float* wc = sm + OFF_WC;

        float4 pf[3];
        {
            const float4* src = (const float4*)g_qkv_wt;
#pragma unroll
            for (int i = 0; i < 3; i++) pf[i] = src[i * 256 + tid];
        }
#pragma unroll 1
        for (int ch = 0; ch < 16; ch++) {
            __syncthreads();                       // buffer free
#pragma unroll
            for (int i = 0; i < 3; i++) {          // STS prefetched chunk (tf32)
                int idx = i * 256 + tid;           // 768 float4 = 8*384/4
                int r = idx / 96, c4 = idx % 96;
                float4 w;
                w.x = __uint_as_float(f2tf(pf[i].x)); w.y = __uint_as_float(f2tf(pf[i].y));
                w.z = __uint_as_float(f2tf(pf[i].z)); w.w = __uint_as_float(f2tf(pf[i].w));
                *(float4*)(wc + r * 388 + c4 * 4) = w;
            }
            if (ch < 15) {                          // LDG next chunk (hidden by mma)
                const float4* src = (const float4*)(g_qkv_wt + (ch + 1) * 8 * 384);
#pragma unroll
                for (int i = 0; i < 3; i++) pf[i] = src[i * 256 + tid];
            }
            __syncthreads();                       // chunk staged

            unsigned a[4][4];
#pragma unroll
            for (int mt = 0; mt < 4; mt++) {
                const float* ap = xs + (mt * 16 + g) * 132 + ch * 8;
                a[mt][0] = __float_as_uint(ap[q4]);
                a[mt][1] = __float_as_uint(ap[8 * 132 + q4]);
                a[mt][2] = __float_as_uint(ap[q4 + 4]);
                a[mt][3] = __float_as_uint(ap[8 * 132 + q4 + 4]);
            }
#pragma unroll
            for (int nt = 0; nt < 6; nt++) {
                int ncol = nb0 + nt * 8 + g;
                unsigned b0 = __float_as_uint(wc[q4 * 388 + ncol]);
                unsigned b1 = __float_as_uint(wc[(q4 + 4) * 388 + ncol]);
#pragma unroll
                for (int mt = 0; mt < 4; mt++) mma8(acc[mt][nt], a[mt], b0, b1);
            }
        }
        // epilogue: qkv = acc + bias
#pragma unroll
        for (int mt = 0; mt < 4; mt++)
#pragma unroll
            for (int nt = 0; nt < 6; nt++) {
                int row = mt * 16 + g, col = nb0 + nt * 8 + 2 * q4;
                float bx = qb[col], by = qb[col + 1];
                *(float2*)(qkv + row * QS + col) =
                    make_float2(acc[mt][nt][0] + bx, acc[mt][nt][1] + by);
                *(float2*)(qkv + (row + 8) * QS + col) =
                    make_float2(acc[mt][nt][2] + bx, acc[mt][nt][3] + by);
            }
    }
    __syncthreads();

    // ---------------- phase 3: attention (warp h, 2 q-rows per lane) --------
    {
        const int h = tr;
        const float scale = 0.25f;

        float qr[2][16];
#pragma unroll
        for (int r = 0; r < 2; r++) {
            const float4* qp = (const float4*)(qkv + (lane + 32 * r) * QS + h * 16);
#pragma unroll
            for (int d4 = 0; d4 < 4; d4++) {
                float4 v = qp[d4];
                qr[r][d4 * 4 + 0] = v.x; qr[r][d4 * 4 + 1] = v.y;
                qr[r][d4 * 4 + 2] = v.z; qr[r][d4 * 4 + 3] = v.w;
            }
        }

        float mrun[2] = {-3e38f, -3e38f};
        float lrun[2] = {0.0f, 0.0f};
        float o[2][16];
#pragma unroll
        for (int r = 0; r < 2; r++)
#pragma unroll
            for (int d = 0; d < 16; d++) o[r][d] = 0.0f;

        const __nv_bfloat16* egh = egs + h * 4096;

        for (int c = 0; c < 4; c++) {
            float s[2][16];
#pragma unroll
            for (int kk = 0; kk < 16; kk++) {
                int k = c * 16 + kk;
                const float4* kp = (const float4*)(qkv + k * QS + 128 + h * 16);
                float kvv[16];
#pragma unroll
                for (int d4 = 0; d4 < 4; d4++) {
                    float4 v = kp[d4];
                    kvv[d4 * 4 + 0] = v.x; kvv[d4 * 4 + 1] = v.y;
                    kvv[d4 * 4 + 2] = v.z; kvv[d4 * 4 + 3] = v.w;
                }
                float d0 = 0.0f, d1 = 0.0f;
#pragma unroll
                for (int d = 0; d < 16; d++) {
                    d0 = fmaf(qr[0][d], kvv[d], d0);
                    d1 = fmaf(qr[1][d], kvv[d], d1);
                }
                int sw = lane ^ (k & 31);
                float lb0 = lb[k * 64 + sw];
                float lb1 = lb[k * 64 + sw + 32];
                float e0 = __bfloat162float(egh[k * 64 + sw]);
                float e1 = __bfloat162float(egh[k * 64 + sw + 32]);
                s[0][kk] = fmaf(d0, scale, lb0) + e0;
                s[1][kk] = fmaf(d1, scale, lb1) + e1;
            }
#pragma unroll
            for (int r = 0; r < 2; r++) {
                float ml = s[r][0];
#pragma unroll
                for (int kk = 1; kk < 16; kk++) ml = fmaxf(ml, s[r][kk]);
                float mnew = fmaxf(mrun[r], ml);
                float corr = __expf(mrun[r] - mnew);
                mrun[r] = mnew;
                lrun[r] *= corr;
#pragma unroll
                for (int d = 0; d < 16; d++) o[r][d] *= corr;
#pragma unroll
                for (int kk = 0; kk < 16; kk++) {
                    float p = __expf(s[r][kk] - mnew);
                    lrun[r] += p;
                    s[r][kk] = p;
                }
            }
#pragma unroll
            for (int kk = 0; kk < 16; kk++) {
                int k = c * 16 + kk;
                const float4* vp = (const float4*)(qkv + k * QS + 256 + h * 16);
                float p0 = s[0][kk], p1 = s[1][kk];
#pragma unroll
                for (int d4 = 0; d4 < 4; d4++) {
                    float4 v = vp[d4];
                    o[0][d4 * 4 + 0] = fmaf(p0, v.x, o[0][d4 * 4 + 0]);
                    o[0][d4 * 4 + 1] = fmaf(p0, v.y, o[0][d4 * 4 + 1]);
                    o[0][d4 * 4 + 2] = fmaf(p0, v.z, o[0][d4 * 4 + 2]);
                    o[0][d4 * 4 + 3] = fmaf(p0, v.w, o[0][d4 * 4 + 3]);
                    o[1][d4 * 4 + 0] = fmaf(p1, v.x, o[1][d4 * 4 + 0]);
                    o[1][d4 * 4 + 1] = fmaf(p1, v.y, o[1][d4 * 4 + 1]);
                    o[1][d4 * 4 + 2] = fmaf(p1, v.z, o[1][d4 * 4 + 2]);
                    o[1][d4 * 4 + 3] = fmaf(p1, v.w, o[1][d4 * 4 + 3]);
                }
            }
        }

        float* outs = sm + OFF_OUTS;          // tf32-rounded for proj mma
#pragma unroll
        for (int r = 0; r < 2; r++) {
            float inv = 1.0f / lrun[r];
#pragma unroll
            for (int d = 0; d < 16; d++)
                outs[(lane + 32 * r) * 132 + h * 16 + d] =
                    __uint_as_float(f2tf(o[r][d] * inv));
        }
    }

    // ---------------- phase 4: output projection via mma --------------------
    {
        float pacc[4][2][4];
#pragma unroll
        for (int mt = 0; mt < 4; mt++)
#pragma unroll
            for (int nt = 0; nt < 2; nt++)
#pragma unroll
                for (int i = 0; i < 4; i++) pacc[mt][nt][i] = 0.0f;

        const int nb0p = tr * 16;
        float* outs = sm + OFF_OUTS;
        float* wp   = sm + OFF_WP;

        float4 pf[2];
        {
            const float4* src = (const float4*)g_proj_wt;
#pragma unroll
            for (int i = 0; i < 2; i++) pf[i] = src[i * 256 + tid];
        }
#pragma unroll 1
        for (int ch = 0; ch < 8; ch++) {
            __syncthreads();                       // Outs ready / buffer free
#pragma unroll
            for (int i = 0; i < 2; i++) {          // STS chunk (16 k-rows, tf32)
                int idx = i * 256 + tid;           // 512 float4 = 16*128/4
                int r = idx >> 5, c4 = idx & 31;
                float4 w;
                w.x = __uint_as_float(f2tf(pf[i].x)); w.y = __uint_as_float(f2tf(pf[i].y));
                w.z = __uint_as_float(f2tf(pf[i].z)); w.w = __uint_as_float(f2tf(pf[i].w));
                *(float4*)(wp + r * 132 + c4 * 4) = w;
            }
            if (ch < 7) {
                const float4* src = (const float4*)(g_proj_wt + (ch + 1) * 16 * 128);
#pragma unroll
                for (int i = 0; i < 2; i++) pf[i] = src[i * 256 + tid];
            }
            __syncthreads();

#pragma unroll
            for (int ks = 0; ks < 2; ks++) {
                int kb = ks * 8;
                unsigned a[4][4];
#pragma unroll
                for (int mt = 0; mt < 4; mt++) {
                    const float* ap = outs + (mt * 16 + g) * 132 + ch * 16 + kb;
                    a[mt][0] = __float_as_uint(ap[q4]);
                    a[mt][1] = __float_as_uint(ap[8 * 132 + q4]);
                    a[mt][2] = __float_as_uint(ap[q4 + 4]);
                    a[mt][3] = __float_as_uint(ap[8 * 132 + q4 + 4]);
                }
#pragma unroll
                for (int nt = 0; nt < 2; nt++) {
                    int ncol = nb0p + nt * 8 + g;
                    unsigned b0 = __float_as_uint(wp[(kb + q4) * 132 + ncol]);
                    unsigned b1 = __float_as_uint(wp[(kb + q4 + 4) * 132 + ncol]);
#pragma unroll
                    for (int mt = 0; mt < 4; mt++) mma8(pacc[mt][nt], a[mt], b0, b1);
                }
            }
        }
        // epilogue: global writes + bias
        float* og = out + row0 * 128;
#pragma unroll
        for (int mt = 0; mt < 4; mt++)
#pragma unroll
            for (int nt = 0; nt < 2; nt++) {
                int row = mt * 16 + g, col = nb0p + nt * 8 + 2 * q4;
                float bx = pb[col], by = pb[col + 1];
                *(float2*)(og + row * 128 + col) =
                    make_float2(pacc[mt][nt][0] + bx, pacc[mt][nt][1] + by);
                *(float2*)(og + (row + 8) * 128 + col) =
                    make_float2(pacc[mt][nt][2] + bx, pacc[mt][nt][3] + by);
            }
    }
}

extern "C" void kernel_launch(void* const* d_in, const int* in_sizes, int n_in,
                              void* d_out, int out_size)
{
    (void)in_sizes; (void)n_in; (void)out_size;
    const float* x      = (const float*)d_in[0];
    const int*   am     = (const int*)  d_in[1];
    const float* ef     = (const float*)d_in[2];
    const float* qkv_w  = (const float*)d_in[3];
    const float* qkv_b  = (const float*)d_in[4];
    const float* proj_w = (const float*)d_in[5];
    const float* proj_b = (const float*)d_in[6];
    const float* eg_w1  = (const float*)d_in[7];
    const float* eg_b1  = (const float*)d_in[8];
    const float* eg_w2  = (const float*)d_in[9];
    const float* eg_b2  = (const float*)d_in[10];
    float* out = (float*)d_out;

    k_transpose_qkv<<<192, 256>>>(qkv_w);
    k_transpose_proj<<<64, 256>>>(proj_w);

    cudaFuncSetAttribute(fused_attn,
                         cudaFuncAttributeMaxDynamicSharedMemorySize, SMEM_BYTES);
    fused_attn<<<1024, 256, SMEM_BYTES>>>(x, am, ef, qkv_b, proj_b,
                                          eg_w1, eg_b1, eg_w2, eg_b2, out);
}

// round 3
// speedup vs baseline: 2.3108x; 1.1169x over previous
#include <cuda_runtime.h>
#include <cuda_bf16.h>

// ---------------------------------------------------------------------------
// LeafOnlyNet fused block-attention kernel, round 3: all GEMMs (QKV, S=QK^T,
// P@V, proj) on tensor pipe via tf32 mma.sync. One CTA per (b,nb) block.
// ---------------------------------------------------------------------------

#define QS 388              // qkv smem row stride (floats)
#define LBS 66              // lb row stride (floats)
#define EGS 68              // eg row stride (bf16)
#define OFF_LB   0                          // lb[q][k]   64*66      = 4224
#define OFF_EG   4224                       // eg[h][q][k] bf16 8*64*68 = 17408 fl
#define OFF_QKV  21632                      // qkv[64][388] = 24832 (outs overlays)
#define OFF_TR   46464                      // transient: Xs[64][132]+Wc[8][388] / Wp[16][132]
#define OFF_XS   OFF_TR
#define OFF_WC   (OFF_TR + 8448)
#define OFF_WP   OFF_TR
#define OFF_NEED 58016
#define SMEM_FLOATS 58080
#define SMEM_BYTES  (SMEM_FLOATS * 4)       // 232320 B

static __device__ __align__(16) float g_qkv_wt[128 * 384];   // Wt[k][c] = qkv_w[c][k]
static __device__ __align__(16) float g_proj_wt[128 * 128];  // Wt[k][c] = proj_w[c][k]

__global__ void k_transpose_qkv(const float* __restrict__ w) {
    int idx = blockIdx.x * 256 + threadIdx.x;
    if (idx < 128 * 384) {
        int k = idx / 384, c = idx % 384;
        g_qkv_wt[idx] = w[c * 128 + k];
    }
}
__global__ void k_transpose_proj(const float* __restrict__ w) {
    int idx = blockIdx.x * 256 + threadIdx.x;
    if (idx < 128 * 128) {
        int k = idx / 128, c = idx % 128;
        g_proj_wt[idx] = w[c * 128 + k];
    }
}

__device__ __forceinline__ unsigned f2tf(float f) {
    unsigned u;
    asm("cvt.rna.tf32.f32 %0, %1;" : "=r"(u) : "f"(f));
    return u;
}

__device__ __forceinline__ void mma8(float* d, const unsigned* a, unsigned b0, unsigned b1) {
    asm volatile(
        "mma.sync.aligned.m16n8k8.row.col.f32.tf32.tf32.f32 "
        "{%0,%1,%2,%3},{%4,%5,%6,%7},{%8,%9},{%0,%1,%2,%3};\n"
        : "+f"(d[0]), "+f"(d[1]), "+f"(d[2]), "+f"(d[3])
        : "r"(a[0]), "r"(a[1]), "r"(a[2]), "r"(a[3]), "r"(b0), "r"(b1));
}

__global__ void __launch_bounds__(256, 1)
fused_attn(const float* __restrict__ x,
           const int*   __restrict__ attn_mask,
           const float* __restrict__ ef,
           const float* __restrict__ qkv_b,
           const float* __restrict__ proj_b,
           const float* __restrict__ eg_w1,
           const float* __restrict__ eg_b1,
           const float* __restrict__ eg_w2,
           const float* __restrict__ eg_b2,
           float* __restrict__ out)
{
    extern __shared__ float sm[];
    float*          lb   = sm + OFF_LB;
    __nv_bfloat16*  egs  = (__nv_bfloat16*)(sm + OFF_EG);
    float*          qkv  = sm + OFF_QKV;
    float*          need = sm + OFF_NEED;

    const int tid  = threadIdx.x;
    const int blk  = blockIdx.x;
    const int tr   = tid >> 5;     // warp id
    const int lane = tid & 31;
    const int g    = lane >> 2;    // mma group row
    const int q4   = lane & 3;     // mma group col
    const long long row0 = (long long)blk * 64;
    const int*   am  = attn_mask + (long long)blk * 4096;
    const float* efb = ef        + (long long)blk * 16384;

    // ---------------- phase 0: need[] + edge-MLP weights ---------------------
    {
        int row = tid >> 2, qt = tid & 3;
        const int4* r4 = (const int4*)(am + row * 64 + qt * 16);
        int s = 0;
#pragma unroll
        for (int i = 0; i < 4; i++) { int4 v = r4[i]; s += v.x + v.y + v.z + v.w; }
        s += __shfl_xor_sync(0xffffffffu, s, 1);
        s += __shfl_xor_sync(0xffffffffu, s, 2);
        if (qt == 0) need[row] = (s < 1) ? 1.0f : 0.0f;
    }
    // edge-MLP weights: [0,64)=w1[j][4], [64,80)=b1, [80,88)=b2, [88,216)=w2t[j][8]
    float* wsm = sm + OFF_TR;
    if (tid < 64)  wsm[tid]      = eg_w1[tid];
    if (tid < 16)  wsm[64 + tid] = eg_b1[tid];
    if (tid < 8)   wsm[80 + tid] = eg_b2[tid];
    if (tid < 128) wsm[88 + tid] = eg_w2[(tid & 7) * 16 + (tid >> 3)];
    __syncthreads();

    // ---------------- phase 1: edge-gate MLP + logit bias + mask ------------
    {
        float b2r[8];
#pragma unroll
        for (int h = 0; h < 8; h++) b2r[h] = wsm[80 + h];

        const float4* ef4 = (const float4*)efb;
        for (int ch = 0; ch < 4; ch++) {
            float4 e[4]; float on[4]; int ki[4], qi[4];
#pragma unroll
            for (int p = 0; p < 4; p++) {
                int idx = (ch * 4 + p) * 256 + tid;
                int q = idx >> 6, k = idx & 63;
                float4 ev = ef4[idx];
                float m = (float)am[idx];
                if (q == k) { ev.x = 0.f; ev.y = 0.f; ev.z = 0.f; ev.w = 1.f;
                              m = fmaxf(m, need[q]); }
                e[p] = ev; on[p] = (m > 0.0f) ? 1.0f : 0.0f; qi[p] = q; ki[p] = k;
            }
            float acc[4][8];
#pragma unroll
            for (int p = 0; p < 4; p++)
#pragma unroll
                for (int h = 0; h < 8; h++) acc[p][h] = b2r[h];
#pragma unroll
            for (int j = 0; j < 16; j++) {
                float4 w  = *(const float4*)(wsm + j * 4);
                float  b  = wsm[64 + j];
                float4 wa = *(const float4*)(wsm + 88 + j * 8);
                float4 wb = *(const float4*)(wsm + 88 + j * 8 + 4);
#pragma unroll
                for (int p = 0; p < 4; p++) {
                    float pre = fmaf(w.x, e[p].x, fmaf(w.y, e[p].y,
                                fmaf(w.z, e[p].z, fmaf(w.w, e[p].w, b))));
                    // gelu(x) ~= 0.5x + 0.39894228 x^2 - 0.06649038 x^4 (|x|<~0.3)
                    float u  = pre * pre;
                    float v  = fmaf(0.39894228f, pre, 0.5f);
                    float wq = -0.06649038f * u;
                    float gl = fmaf(wq, u, pre * v);
                    acc[p][0] = fmaf(gl, wa.x, acc[p][0]);
                    acc[p][1] = fmaf(gl, wa.y, acc[p][1]);
                    acc[p][2] = fmaf(gl, wa.z, acc[p][2]);
                    acc[p][3] = fmaf(gl, wa.w, acc[p][3]);
                    acc[p][4] = fmaf(gl, wb.x, acc[p][4]);
                    acc[p][5] = fmaf(gl, wb.y, acc[p][5]);
                    acc[p][6] = fmaf(gl, wb.z, acc[p][6]);
                    acc[p][7] = fmaf(gl, wb.w, acc[p][7]);
                }
            }
#pragma unroll
            for (int p = 0; p < 4; p++) {
                int q = qi[p], k = ki[p];
                bool o = on[p] > 0.0f;
                lb[q * LBS + k] = o ? e[p].w : -1e9f;
                int beg = q * EGS + k;
#pragma unroll
                for (int h = 0; h < 8; h++)
                    egs[h * (64 * EGS) + beg] = __float2bfloat16(o ? acc[p][h] : 0.0f);
            }
        }
    }
    __syncthreads();

    // ---------------- phase 2: load X (tf32), QKV via mma -------------------
    {
        float* xs = sm + OFF_XS;
        const float4* xg4 = (const float4*)(x + row0 * 128);
#pragma unroll
        for (int i = 0; i < 8; i++) {
            int idx = i * 256 + tid;
            float4 v = xg4[idx];
            int r = idx >> 5, c4 = idx & 31;
            float4 w;
            w.x = __uint_as_float(f2tf(v.x)); w.y = __uint_as_float(f2tf(v.y));
            w.z = __uint_as_float(f2tf(v.z)); w.w = __uint_as_float(f2tf(v.w));
            *(float4*)(xs + r * 132 + c4 * 4) = w;
        }
    }

    {
        float acc[4][6][4];
#pragma unroll
        for (int mt = 0; mt < 4; mt++)
#pragma unroll
            for (int nt = 0; nt < 6; nt++)
#pragma unroll
                for (int i = 0; i < 4; i++) acc[mt][nt][i] = 0.0f;

        const int nb0 = tr * 48;
        float* xs = sm + OFF_XS;
        float* wc = sm + OFF_WC;

        float4 pf[3];
        {
            const float4* src = (const float4*)g_qkv_wt;
#pragma unroll
            for (int i = 0; i < 3; i++) pf[i] = src[i * 256 + tid];
        }
#pragma unroll 1
        for (int ch = 0; ch < 16; ch++) {
            __syncthreads();                       // buffer free
#pragma unroll
            for (int i = 0; i < 3; i++) {          // STS prefetched chunk (tf32)
                int idx = i * 256 + tid;           // 768 float4 = 8*384/4
                int r = idx / 96, c4 = idx % 96;
                float4 w;
                w.x = __uint_as_float(f2tf(pf[i].x)); w.y = __uint_as_float(f2tf(pf[i].y));
                w.z = __uint_as_float(f2tf(pf[i].z)); w.w = __uint_as_float(f2tf(pf[i].w));
                *(float4*)(wc + r * 388 + c4 * 4) = w;
            }
            if (ch < 15) {
                const float4* src = (const float4*)(g_qkv_wt + (ch + 1) * 8 * 384);
#pragma unroll
                for (int i = 0; i < 3; i++) pf[i] = src[i * 256 + tid];
            }
            __syncthreads();                       // chunk staged

            unsigned a[4][4];
#pragma unroll
            for (int mt = 0; mt < 4; mt++) {
                const float* ap = xs + (mt * 16 + g) * 132 + ch * 8;
                a[mt][0] = __float_as_uint(ap[q4]);
                a[mt][1] = __float_as_uint(ap[8 * 132 + q4]);
                a[mt][2] = __float_as_uint(ap[q4 + 4]);
                a[mt][3] = __float_as_uint(ap[8 * 132 + q4 + 4]);
            }
#pragma unroll
            for (int nt = 0; nt < 6; nt++) {
                int ncol = nb0 + nt * 8 + g;
                unsigned b0 = __float_as_uint(wc[q4 * 388 + ncol]);
                unsigned b1 = __float_as_uint(wc[(q4 + 4) * 388 + ncol]);
#pragma unroll
                for (int mt = 0; mt < 4; mt++) mma8(acc[mt][nt], a[mt], b0, b1);
            }
        }
        // epilogue: qkv = tf32((acc + bias) * scale); fold softmax 1/4 into Q
#pragma unroll
        for (int mt = 0; mt < 4; mt++)
#pragma unroll
            for (int nt = 0; nt < 6; nt++) {
                int row = mt * 16 + g, col = nb0 + nt * 8 + 2 * q4;
                float bx = __ldg(qkv_b + col), by = __ldg(qkv_b + col + 1);
                float sc = (col < 128) ? 0.25f : 1.0f;
                float2 v0, v1;
                v0.x = __uint_as_float(f2tf((acc[mt][nt][0] + bx) * sc));
                v0.y = __uint_as_float(f2tf((acc[mt][nt][1] + by) * sc));
                v1.x = __uint_as_float(f2tf((acc[mt][nt][2] + bx) * sc));
                v1.y = __uint_as_float(f2tf((acc[mt][nt][3] + by) * sc));
                *(float2*)(qkv + row * QS + col)       = v0;
                *(float2*)(qkv + (row + 8) * QS + col) = v1;
            }
    }
    __syncthreads();

    // ---------------- phase 3: attention via mma (warp = head) --------------
    {
        const int h = tr;
        // Q A-fragments (scale pre-folded, tf32-rounded in smem)
        unsigned qa[4][2][4];
#pragma unroll
        for (int mt = 0; mt < 4; mt++)
#pragma unroll
            for (int kt = 0; kt < 2; kt++) {
                const float* ap = qkv + (mt * 16 + g) * QS + 16 * h + kt * 8;
                qa[mt][kt][0] = __float_as_uint(ap[q4]);
                qa[mt][kt][1] = __float_as_uint(ap[8 * QS + q4]);
                qa[mt][kt][2] = __float_as_uint(ap[q4 + 4]);
                qa[mt][kt][3] = __float_as_uint(ap[8 * QS + q4 + 4]);
            }

        float o[4][2][4];
        float mr[4][2], lsm[4][2];
#pragma unroll
        for (int mt = 0; mt < 4; mt++) {
#pragma unroll
            for (int nt = 0; nt < 2; nt++)
#pragma unroll
                for (int i = 0; i < 4; i++) o[mt][nt][i] = 0.0f;
            mr[mt][0] = -1e30f; mr[mt][1] = -1e30f;
            lsm[mt][0] = 0.0f;  lsm[mt][1] = 0.0f;
        }

        const unsigned* egw = (const unsigned*)(sm + OFF_EG) + h * (64 * EGS / 2);
        const int l0i = (g << 2) | (q4 >> 1);
        const int l2i = l0i + 2;
        const bool hiSel = (q4 & 1) != 0;

        for (int c = 0; c < 4; c++) {
            const int kb = c * 16;
            // K B-fragments
            unsigned kbf[2][2][2];
#pragma unroll
            for (int nt = 0; nt < 2; nt++)
#pragma unroll
                for (int kt = 0; kt < 2; kt++) {
                    const float* kp = qkv + (kb + nt * 8 + g) * QS + 128 + 16 * h + kt * 8;
                    kbf[nt][kt][0] = __float_as_uint(kp[q4]);
                    kbf[nt][kt][1] = __float_as_uint(kp[q4 + 4]);
                }
            // S = Q K^T (scale folded)
            float s[4][2][4];
#pragma unroll
            for (int mt = 0; mt < 4; mt++)
#pragma unroll
                for (int nt = 0; nt < 2; nt++) {
#pragma unroll
                    for (int i = 0; i < 4; i++) s[mt][nt][i] = 0.0f;
                    mma8(s[mt][nt], qa[mt][0], kbf[nt][0][0], kbf[nt][0][1]);
                    mma8(s[mt][nt], qa[mt][1], kbf[nt][1][0], kbf[nt][1][1]);
                }
            // + logit bias + edge gate (masked entries: lb = -1e9, eg = 0)
#pragma unroll
            for (int mt = 0; mt < 4; mt++)
#pragma unroll
                for (int nt = 0; nt < 2; nt++) {
                    int q0 = mt * 16 + g;
                    int kc = kb + nt * 8 + 2 * q4;
                    float2 l0 = *(const float2*)(lb + q0 * LBS + kc);
                    float2 l1 = *(const float2*)(lb + (q0 + 8) * LBS + kc);
                    unsigned e0 = egw[q0 * (EGS / 2) + (kc >> 1)];
                    unsigned e1 = egw[(q0 + 8) * (EGS / 2) + (kc >> 1)];
                    s[mt][nt][0] += l0.x + __uint_as_float(e0 << 16);
                    s[mt][nt][1] += l0.y + __uint_as_float(e0 & 0xFFFF0000u);
                    s[mt][nt][2] += l1.x + __uint_as_float(e1 << 16);
                    s[mt][nt][3] += l1.y + __uint_as_float(e1 & 0xFFFF0000u);
                }
            // online softmax per row (row owners == fragment row distribution)
#pragma unroll
            for (int mt = 0; mt < 4; mt++)
#pragma unroll
                for (int rh = 0; rh < 2; rh++) {
                    int i0 = rh * 2;
                    float mp = fmaxf(fmaxf(s[mt][0][i0], s[mt][0][i0 + 1]),
                                     fmaxf(s[mt][1][i0], s[mt][1][i0 + 1]));
                    mp = fmaxf(mp, __shfl_xor_sync(0xffffffffu, mp, 1));
                    mp = fmaxf(mp, __shfl_xor_sync(0xffffffffu, mp, 2));
                    float mnew = fmaxf(mr[mt][rh], mp);
                    float corr = __expf(mr[mt][rh] - mnew);
                    mr[mt][rh] = mnew;
                    float ps = 0.0f;
#pragma unroll
                    for (int nt = 0; nt < 2; nt++)
#pragma unroll
                        for (int e2 = 0; e2 < 2; e2++) {
                            float p = __expf(s[mt][nt][i0 + e2] - mnew);
                            s[mt][nt][i0 + e2] = p;
                            ps += p;
                        }
                    lsm[mt][rh] = lsm[mt][rh] * corr + ps;
#pragma unroll
                    for (int nt = 0; nt < 2; nt++) {
                        o[mt][nt][i0]     *= corr;
                        o[mt][nt][i0 + 1] *= corr;
                    }
                }
            // V B-fragments
            unsigned vb[2][2][2];
#pragma unroll
            for (int t = 0; t < 2; t++)
#pragma unroll
                for (int nd = 0; nd < 2; nd++) {
                    const float* vp = qkv + (kb + t * 8 + q4) * QS + 256 + 16 * h + nd * 8 + g;
                    vb[t][nd][0] = __float_as_uint(vp[0]);
                    vb[t][nd][1] = __float_as_uint(vp[4 * QS]);
                }
            // P: C-frag -> A-frag via shuffle transpose; O += P V
#pragma unroll
            for (int mt = 0; mt < 4; mt++)
#pragma unroll
                for (int t = 0; t < 2; t++) {
                    unsigned p0 = f2tf(s[mt][t][0]), p1 = f2tf(s[mt][t][1]);
                    unsigned p2 = f2tf(s[mt][t][2]), p3 = f2tf(s[mt][t][3]);
                    unsigned v00 = __shfl_sync(0xffffffffu, p0, l0i);
                    unsigned v01 = __shfl_sync(0xffffffffu, p1, l0i);
                    unsigned v02 = __shfl_sync(0xffffffffu, p2, l0i);
                    unsigned v03 = __shfl_sync(0xffffffffu, p3, l0i);
                    unsigned v20 = __shfl_sync(0xffffffffu, p0, l2i);
                    unsigned v21 = __shfl_sync(0xffffffffu, p1, l2i);
                    unsigned v22 = __shfl_sync(0xffffffffu, p2, l2i);
                    unsigned v23 = __shfl_sync(0xffffffffu, p3, l2i);
                    unsigned a[4];
                    a[0] = hiSel ? v01 : v00;
                    a[1] = hiSel ? v03 : v02;
                    a[2] = hiSel ? v21 : v20;
                    a[3] = hiSel ? v23 : v22;
                    mma8(o[mt][0], a, vb[t][0][0], vb[t][0][1]);
                    mma8(o[mt][1], a, vb[t][1][0], vb[t][1][1]);
                }
        }
        // finalize 1/l
        float inv[4][2];
#pragma unroll
        for (int mt = 0; mt < 4; mt++)
#pragma unroll
            for (int rh = 0; rh < 2; rh++) {
                float l = lsm[mt][rh];
                l += __shfl_xor_sync(0xffffffffu, l, 1);
                l += __shfl_xor_sync(0xffffffffu, l, 2);
                inv[mt][rh] = 1.0f / l;
            }
        __syncthreads();                 // all warps done reading qkv
        float* outs = sm + OFF_QKV;      // reuse qkv region; stride 132
#pragma unroll
        for (int mt = 0; mt < 4; mt++)
#pragma unroll
            for (int nd = 0; nd < 2; nd++) {
                int row = mt * 16 + g, col = 16 * h + nd * 8 + 2 * q4;
                float2 v0, v1;
                v0.x = __uint_as_float(f2tf(o[mt][nd][0] * inv[mt][0]));
                v0.y = __uint_as_float(f2tf(o[mt][nd][1] * inv[mt][0]));
                v1.x = __uint_as_float(f2tf(o[mt][nd][2] * inv[mt][1]));
                v1.y = __uint_as_float(f2tf(o[mt][nd][3] * inv[mt][1]));
                *(float2*)(outs + row * 132 + col)       = v0;
                *(float2*)(outs + (row + 8) * 132 + col) = v1;
            }
    }

    // ---------------- phase 4: output projection via mma --------------------
    {
        float pacc[4][2][4];
#pragma unroll
        for (int mt = 0; mt < 4; mt++)
#pragma unroll
            for (int nt = 0; nt < 2; nt++)
#pragma unroll
                for (int i = 0; i < 4; i++) pacc[mt][nt][i] = 0.0f;

        const int nb0p = tr * 16;
        float* outs = sm + OFF_QKV;
        float* wp   = sm + OFF_WP;

        float4 pf[2];
        {
            const float4* src = (const float4*)g_proj_wt;
#pragma unroll
            for (int i = 0; i < 2; i++) pf[i] = src[i * 256 + tid];
        }
#pragma unroll 1
        for (int ch = 0; ch < 8; ch++) {
            __syncthreads();                       // outs ready / buffer free
#pragma unroll
            for (int i = 0; i < 2; i++) {          // STS chunk (16 k-rows, tf32)
                int idx = i * 256 + tid;           // 512 float4 = 16*128/4
                int r = idx >> 5, c4 = idx & 31;
                float4 w;
                w.x = __uint_as_float(f2tf(pf[i].x)); w.y = __uint_as_float(f2tf(pf[i].y));
                w.z = __uint_as_float(f2tf(pf[i].z)); w.w = __uint_as_float(f2tf(pf[i].w));
                *(float4*)(wp + r * 132 + c4 * 4) = w;
            }
            if (ch < 7) {
                const float4* src = (const float4*)(g_proj_wt + (ch + 1) * 16 * 128);
#pragma unroll
                for (int i = 0; i < 2; i++) pf[i] = src[i * 256 + tid];
            }
            __syncthreads();

#pragma unroll
            for (int ks = 0; ks < 2; ks++) {
                int kb = ks * 8;
                unsigned a[4][4];
#pragma unroll
                for (int mt = 0; mt < 4; mt++) {
                    const float* ap = outs + (mt * 16 + g) * 132 + ch * 16 + kb;
                    a[mt][0] = __float_as_uint(ap[q4]);
                    a[mt][1] = __float_as_uint(ap[8 * 132 + q4]);
                    a[mt][2] = __float_as_uint(ap[q4 + 4]);
                    a[mt][3] = __float_as_uint(ap[8 * 132 + q4 + 4]);
                }
#pragma unroll
                for (int nt = 0; nt < 2; nt++) {
                    int ncol = nb0p + nt * 8 + g;
                    unsigned b0 = __float_as_uint(wp[(kb + q4) * 132 + ncol]);
                    unsigned b1 = __float_as_uint(wp[(kb + q4 + 4) * 132 + ncol]);
#pragma unroll
                    for (int mt = 0; mt < 4; mt++) mma8(pacc[mt][nt], a[mt], b0, b1);
                }
            }
        }
        // epilogue: global writes + bias
        float* og = out + row0 * 128;
#pragma unroll
        for (int mt = 0; mt < 4; mt++)
#pragma unroll
            for (int nt = 0; nt < 2; nt++) {
                int row = mt * 16 + g, col = nb0p + nt * 8 + 2 * q4;
                float bx = __ldg(proj_b + col), by = __ldg(proj_b + col + 1);
                *(float2*)(og + row * 128 + col) =
                    make_float2(pacc[mt][nt][0] + bx, pacc[mt][nt][1] + by);
                *(float2*)(og + (row + 8) * 128 + col) =
                    make_float2(pacc[mt][nt][2] + bx, pacc[mt][nt][3] + by);
            }
    }
}

extern "C" void kernel_launch(void* const* d_in, const int* in_sizes, int n_in,
                              void* d_out, int out_size)
{
    (void)in_sizes; (void)n_in; (void)out_size;
    const float* x      = (const float*)d_in[0];
    const int*   am     = (const int*)  d_in[1];
    const float* ef     = (const float*)d_in[2];
    const float* qkv_w  = (const float*)d_in[3];
    const float* qkv_b  = (const float*)d_in[4];
    const float* proj_w = (const float*)d_in[5];
    const float* proj_b = (const float*)d_in[6];
    const float* eg_w1  = (const float*)d_in[7];
    const float* eg_b1  = (const float*)d_in[8];
    const float* eg_w2  = (const float*)d_in[9];
    const float* eg_b2  = (const float*)d_in[10];
    float* out = (float*)d_out;

    k_transpose_qkv<<<192, 256>>>(qkv_w);
    k_transpose_proj<<<64, 256>>>(proj_w);

    cudaFuncSetAttribute(fused_attn,
                         cudaFuncAttributeMaxDynamicSharedMemorySize, SMEM_BYTES);
    fused_attn<<<1024, 256, SMEM_BYTES>>>(x, am, ef, qkv_b, proj_b,
                                          eg_w1, eg_b1, eg_w2, eg_b2, out);
}

// round 4
// speedup vs baseline: 2.3136x; 1.0012x over previous
#include <cuda_runtime.h>
#include <cuda_bf16.h>

// ---------------------------------------------------------------------------
// LeafOnlyNet fused block-attention kernel, round 4: tf32 mma GEMMs +
// f32x2 packed-FMA edge MLP. One CTA per (b,nb) block, 256 threads.
// ---------------------------------------------------------------------------

#define QS 388              // qkv smem row stride (floats)
#define LBS 66              // lb row stride (floats)
#define EGS 68              // eg row stride (bf16)
#define OFF_LB   0                          // lb[q][k]   64*66      = 4224
#define OFF_EG   4224                       // eg[h][q][k] bf16 8*64*68 = 17408 fl
#define OFF_QKV  21632                      // qkv[64][388] = 24832 (outs overlays)
#define OFF_TR   46464                      // transient: Xs[64][132]+Wc[8][388] / Wp[16][132]
#define OFF_XS   OFF_TR
#define OFF_WC   (OFF_TR + 8448)
#define OFF_WP   OFF_TR
#define OFF_NEED 58016
#define SMEM_FLOATS 58080
#define SMEM_BYTES  (SMEM_FLOATS * 4)       // 232320 B

static __device__ __align__(16) float g_qkv_wt[128 * 384];   // Wt[k][c] = qkv_w[c][k]
static __device__ __align__(16) float g_proj_wt[128 * 128];  // Wt[k][c] = proj_w[c][k]

__global__ void k_transpose_w(const float* __restrict__ qw,
                              const float* __restrict__ pw) {
    int idx = blockIdx.x * 256 + threadIdx.x;
    if (idx < 128 * 384) {
        int k = idx / 384, c = idx % 384;
        g_qkv_wt[idx] = qw[c * 128 + k];
    }
    int j = idx - 128 * 384;
    if (j >= 0 && j < 128 * 128) {
        int k = j / 128, c = j % 128;
        g_proj_wt[j] = pw[c * 128 + k];
    }
}

__device__ __forceinline__ unsigned f2tf(float f) {
    unsigned u;
    asm("cvt.rna.tf32.f32 %0, %1;" : "=r"(u) : "f"(f));
    return u;
}

__device__ __forceinline__ void mma8(float* d, const unsigned* a, unsigned b0, unsigned b1) {
    asm volatile(
        "mma.sync.aligned.m16n8k8.row.col.f32.tf32.tf32.f32 "
        "{%0,%1,%2,%3},{%4,%5,%6,%7},{%8,%9},{%0,%1,%2,%3};\n"
        : "+f"(d[0]), "+f"(d[1]), "+f"(d[2]), "+f"(d[3])
        : "r"(a[0]), "r"(a[1]), "r"(a[2]), "r"(a[3]), "r"(b0), "r"(b1));
}

// ---- f32x2 packed helpers (sm_100+) ----
typedef unsigned long long u64t;
__device__ __forceinline__ u64t pk2(float a, float b) {
    u64t r; asm("mov.b64 %0, {%1, %2};" : "=l"(r) : "f"(a), "f"(b)); return r;
}
__device__ __forceinline__ void upk2(u64t v, float& a, float& b) {
    asm("mov.b64 {%0, %1}, %2;" : "=f"(a), "=f"(b) : "l"(v));
}
__device__ __forceinline__ u64t fma2(u64t a, u64t b, u64t c) {
    u64t d; asm("fma.rn.f32x2 %0, %1, %2, %3;" : "=l"(d) : "l"(a), "l"(b), "l"(c)); return d;
}
__device__ __forceinline__ u64t mul2(u64t a, u64t b) {
    u64t d; asm("mul.rn.f32x2 %0, %1, %2;" : "=l"(d) : "l"(a), "l"(b)); return d;
}

__global__ void __launch_bounds__(256, 1)
fused_attn(const float* __restrict__ x,
           const int*   __restrict__ attn_mask,
           const float* __restrict__ ef,
           const float* __restrict__ qkv_b,
           const float* __restrict__ proj_b,
           const float* __restrict__ eg_w1,
           const float* __restrict__ eg_b1,
           const float* __restrict__ eg_w2,
           const float* __restrict__ eg_b2,
           float* __restrict__ out)
{
    extern __shared__ float sm[];
    float*          lb   = sm + OFF_LB;
    __nv_bfloat16*  egs  = (__nv_bfloat16*)(sm + OFF_EG);
    float*          qkv  = sm + OFF_QKV;
    float*          need = sm + OFF_NEED;

    const int tid  = threadIdx.x;
    const int blk  = blockIdx.x;
    const int tr   = tid >> 5;     // warp id
    const int lane = tid & 31;
    const int g    = lane >> 2;    // mma group row
    const int q4   = lane & 3;     // mma group col
    const long long row0 = (long long)blk * 64;
    const int*   am  = attn_mask + (long long)blk * 4096;
    const float* efb = ef        + (long long)blk * 16384;

    // ---------------- phase 0: need[] + edge-MLP weights (duplicated) -------
    {
        int row = tid >> 2, qt = tid & 3;
        const int4* r4 = (const int4*)(am + row * 64 + qt * 16);
        int s = 0;
#pragma unroll
        for (int i = 0; i < 4; i++) { int4 v = r4[i]; s += v.x + v.y + v.z + v.w; }
        s += __shfl_xor_sync(0xffffffffu, s, 1);
        s += __shfl_xor_sync(0xffffffffu, s, 2);
        if (qt == 0) need[row] = (s < 1) ? 1.0f : 0.0f;
    }
    // wsm layout: [0,8)=b2, [8,136)=w1 dup (j*8+c*2+d), [136,168)=b1 dup (j*2+d),
    //             [168,424)=w2t dup (j*16+h*2+d)
    float* wsm = sm + OFF_TR;
    if (tid < 8) wsm[tid] = eg_b2[tid];
    if (tid < 128) {
        int j = tid >> 3, c = (tid >> 1) & 3;
        wsm[8 + tid] = eg_w1[j * 4 + c];
    }
    if (tid < 32) wsm[136 + tid] = eg_b1[tid >> 1];
    {
        int j = tid >> 4, h = (tid >> 1) & 7;
        wsm[168 + tid] = eg_w2[h * 16 + j];
    }
    __syncthreads();

    // ---------------- phase 1: edge-gate MLP (f32x2 packed) -----------------
    {
        u64t b22[8];
#pragma unroll
        for (int h = 0; h < 8; h++) { float b = wsm[h]; b22[h] = pk2(b, b); }
        const u64t C05 = pk2(0.5f, 0.5f);
        const u64t C1  = pk2(0.39894228f, 0.39894228f);
        const u64t C2  = pk2(-0.06649038f, -0.06649038f);

        const float4* ef4 = (const float4*)efb;
        for (int ch = 0; ch < 4; ch++) {
            float4 e[4]; float on[4]; int ki[4], qi[4];
#pragma unroll
            for (int p = 0; p < 4; p++) {
                int idx = (ch * 4 + p) * 256 + tid;
                int q = idx >> 6, k = idx & 63;
                float4 ev = ef4[idx];
                float m = (float)am[idx];
                if (q == k) { ev.x = 0.f; ev.y = 0.f; ev.z = 0.f; ev.w = 1.f;
                              m = fmaxf(m, need[q]); }
                e[p] = ev; on[p] = (m > 0.0f) ? 1.0f : 0.0f; qi[p] = q; ki[p] = k;
            }
            u64t ex2[2], ey2[2], ez2[2], ew2[2];
#pragma unroll
            for (int s = 0; s < 2; s++) {
                ex2[s] = pk2(e[2 * s].x, e[2 * s + 1].x);
                ey2[s] = pk2(e[2 * s].y, e[2 * s + 1].y);
                ez2[s] = pk2(e[2 * s].z, e[2 * s + 1].z);
                ew2[s] = pk2(e[2 * s].w, e[2 * s + 1].w);
            }
            u64t acc2[2][8];
#pragma unroll
            for (int s = 0; s < 2; s++)
#pragma unroll
                for (int h = 0; h < 8; h++) acc2[s][h] = b22[h];

#pragma unroll
            for (int j = 0; j < 16; j++) {
                u64t wx = *(const u64t*)(wsm + 8 + j * 8);
                u64t wy = *(const u64t*)(wsm + 8 + j * 8 + 2);
                u64t wz = *(const u64t*)(wsm + 8 + j * 8 + 4);
                u64t ww = *(const u64t*)(wsm + 8 + j * 8 + 6);
                u64t b1 = *(const u64t*)(wsm + 136 + j * 2);
                u64t gl[2];
#pragma unroll
                for (int s = 0; s < 2; s++) {
                    u64t pre = fma2(wx, ex2[s], fma2(wy, ey2[s],
                               fma2(wz, ez2[s], fma2(ww, ew2[s], b1))));
                    // gelu(x) ~= 0.5x + 0.39894228 x^2 - 0.06649038 x^4
                    u64t u  = mul2(pre, pre);
                    u64t v  = fma2(C1, pre, C05);
                    u64t pv = mul2(pre, v);
                    u64t wq = mul2(C2, u);
                    gl[s] = fma2(wq, u, pv);
                }
#pragma unroll
                for (int h = 0; h < 8; h++) {
                    u64t wa = *(const u64t*)(wsm + 168 + j * 16 + h * 2);
                    acc2[0][h] = fma2(gl[0], wa, acc2[0][h]);
                    acc2[1][h] = fma2(gl[1], wa, acc2[1][h]);
                }
            }
#pragma unroll
            for (int p = 0; p < 4; p++)
                lb[qi[p] * LBS + ki[p]] = (on[p] > 0.0f) ? e[p].w : -1e9f;
#pragma unroll
            for (int s = 0; s < 2; s++) {
                int p0 = 2 * s, p1 = 2 * s + 1;
                int beg0 = qi[p0] * EGS + ki[p0];
                int beg1 = qi[p1] * EGS + ki[p1];
                bool o0 = on[p0] > 0.0f, o1 = on[p1] > 0.0f;
#pragma unroll
                for (int h = 0; h < 8; h++) {
                    float a0, a1;
                    upk2(acc2[s][h], a0, a1);
                    egs[h * (64 * EGS) + beg0] = __float2bfloat16(o0 ? a0 : 0.0f);
                    egs[h * (64 * EGS) + beg1] = __float2bfloat16(o1 ? a1 : 0.0f);
                }
            }
        }
    }
    __syncthreads();

    // ---------------- phase 2: load X (tf32), QKV via mma -------------------
    {
        float* xs = sm + OFF_XS;
        const float4* xg4 = (const float4*)(x + row0 * 128);
#pragma unroll
        for (int i = 0; i < 8; i++) {
            int idx = i * 256 + tid;
            float4 v = xg4[idx];
            int r = idx >> 5, c4 = idx & 31;
            float4 w;
            w.x = __uint_as_float(f2tf(v.x)); w.y = __uint_as_float(f2tf(v.y));
            w.z = __uint_as_float(f2tf(v.z)); w.w = __uint_as_float(f2tf(v.w));
            *(float4*)(xs + r * 132 + c4 * 4) = w;
        }
    }

    {
        float acc[4][6][4];
#pragma unroll
        for (int mt = 0; mt < 4; mt++)
#pragma unroll
            for (int nt = 0; nt < 6; nt++)
#pragma unroll
                for (int i = 0; i < 4; i++) acc[mt][nt][i] = 0.0f;

        const int nb0 = tr * 48;
        float* xs = sm + OFF_XS;
        float* wc = sm + OFF_WC;

        float4 pf[3];
        {
            const float4* src = (const float4*)g_qkv_wt;
#pragma unroll
            for (int i = 0; i < 3; i++) pf[i] = src[i * 256 + tid];
        }
#pragma unroll 1
        for (int ch = 0; ch < 16; ch++) {
            __syncthreads();                       // buffer free
#pragma unroll
            for (int i = 0; i < 3; i++) {          // STS prefetched chunk (tf32)
                int idx = i * 256 + tid;           // 768 float4 = 8*384/4
                int r = idx / 96, c4 = idx % 96;
                float4 w;
                w.x = __uint_as_float(f2tf(pf[i].x)); w.y = __uint_as_float(f2tf(pf[i].y));
                w.z = __uint_as_float(f2tf(pf[i].z)); w.w = __uint_as_float(f2tf(pf[i].w));
                *(float4*)(wc + r * 388 + c4 * 4) = w;
            }
            if (ch < 15) {
                const float4* src = (const float4*)(g_qkv_wt + (ch + 1) * 8 * 384);
#pragma unroll
                for (int i = 0; i < 3; i++) pf[i] = src[i * 256 + tid];
            }
            __syncthreads();                       // chunk staged

            unsigned a[4][4];
#pragma unroll
            for (int mt = 0; mt < 4; mt++) {
                const float* ap = xs + (mt * 16 + g) * 132 + ch * 8;
                a[mt][0] = __float_as_uint(ap[q4]);
                a[mt][1] = __float_as_uint(ap[8 * 132 + q4]);
                a[mt][2] = __float_as_uint(ap[q4 + 4]);
                a[mt][3] = __float_as_uint(ap[8 * 132 + q4 + 4]);
            }
#pragma unroll
            for (int nt = 0; nt < 6; nt++) {
                int ncol = nb0 + nt * 8 + g;
                unsigned b0 = __float_as_uint(wc[q4 * 388 + ncol]);
                unsigned b1 = __float_as_uint(wc[(q4 + 4) * 388 + ncol]);
#pragma unroll
                for (int mt = 0; mt < 4; mt++) mma8(acc[mt][nt], a[mt], b0, b1);
            }
        }
        // epilogue: qkv = tf32((acc + bias) * scale); fold softmax 1/4 into Q
#pragma unroll
        for (int mt = 0; mt < 4; mt++)
#pragma unroll
            for (int nt = 0; nt < 6; nt++) {
                int row = mt * 16 + g, col = nb0 + nt * 8 + 2 * q4;
                float bx = __ldg(qkv_b + col), by = __ldg(qkv_b + col + 1);
                float sc = (col < 128) ? 0.25f : 1.0f;
                float2 v0, v1;
                v0.x = __uint_as_float(f2tf((acc[mt][nt][0] + bx) * sc));
                v0.y = __uint_as_float(f2tf((acc[mt][nt][1] + by) * sc));
                v1.x = __uint_as_float(f2tf((acc[mt][nt][2] + bx) * sc));
                v1.y = __uint_as_float(f2tf((acc[mt][nt][3] + by) * sc));
                *(float2*)(qkv + row * QS + col)       = v0;
                *(float2*)(qkv + (row + 8) * QS + col) = v1;
            }
    }
    __syncthreads();

    // ---------------- phase 3: attention via mma (warp = head) --------------
    {
        const int h = tr;
        // Q A-fragments (scale pre-folded, tf32-rounded in smem)
        unsigned qa[4][2][4];
#pragma unroll
        for (int mt = 0; mt < 4; mt++)
#pragma unroll
            for (int kt = 0; kt < 2; kt++) {
                const float* ap = qkv + (mt * 16 + g) * QS + 16 * h + kt * 8;
                qa[mt][kt][0] = __float_as_uint(ap[q4]);
                qa[mt][kt][1] = __float_as_uint(ap[8 * QS + q4]);
                qa[mt][kt][2] = __float_as_uint(ap[q4 + 4]);
                qa[mt][kt][3] = __float_as_uint(ap[8 * QS + q4 + 4]);
            }

        float o[4][2][4];
        float mr[4][2], lsm[4][2];
#pragma unroll
        for (int mt = 0; mt < 4; mt++) {
#pragma unroll
            for (int nt = 0; nt < 2; nt++)
#pragma unroll
                for (int i = 0; i < 4; i++) o[mt][nt][i] = 0.0f;
            mr[mt][0] = -1e30f; mr[mt][1] = -1e30f;
            lsm[mt][0] = 0.0f;  lsm[mt][1] = 0.0f;
        }

        const unsigned* egw = (const unsigned*)(sm + OFF_EG) + h * (64 * EGS / 2);
        const int l0i = (g << 2) | (q4 >> 1);
        const int l2i = l0i + 2;
        const bool hiSel = (q4 & 1) != 0;

        for (int c = 0; c < 4; c++) {
            const int kb = c * 16;
            // K B-fragments
            unsigned kbf[2][2][2];
#pragma unroll
            for (int nt = 0; nt < 2; nt++)
#pragma unroll
                for (int kt = 0; kt < 2; kt++) {
                    const float* kp = qkv + (kb + nt * 8 + g) * QS + 128 + 16 * h + kt * 8;
                    kbf[nt][kt][0] = __float_as_uint(kp[q4]);
                    kbf[nt][kt][1] = __float_as_uint(kp[q4 + 4]);
                }
            // S = Q K^T (scale folded)
            float s[4][2][4];
#pragma unroll
            for (int mt = 0; mt < 4; mt++)
#pragma unroll
                for (int nt = 0; nt < 2; nt++) {
#pragma unroll
                    for (int i = 0; i < 4; i++) s[mt][nt][i] = 0.0f;
                    mma8(s[mt][nt], qa[mt][0], kbf[nt][0][0], kbf[nt][0][1]);
                    mma8(s[mt][nt], qa[mt][1], kbf[nt][1][0], kbf[nt][1][1]);
                }
            // + logit bias + edge gate (masked entries: lb = -1e9, eg = 0)
#pragma unroll
            for (int mt = 0; mt < 4; mt++)
#pragma unroll
                for (int nt = 0; nt < 2; nt++) {
                    int q0 = mt * 16 + g;
                    int kc = kb + nt * 8 + 2 * q4;
                    float2 l0 = *(const float2*)(lb + q0 * LBS + kc);
                    float2 l1 = *(const float2*)(lb + (q0 + 8) * LBS + kc);
                    unsigned e0 = egw[q0 * (EGS / 2) + (kc >> 1)];
                    unsigned e1 = egw[(q0 + 8) * (EGS / 2) + (kc >> 1)];
                    s[mt][nt][0] += l0.x + __uint_as_float(e0 << 16);
                    s[mt][nt][1] += l0.y + __uint_as_float(e0 & 0xFFFF0000u);
                    s[mt][nt][2] += l1.x + __uint_as_float(e1 << 16);
                    s[mt][nt][3] += l1.y + __uint_as_float(e1 & 0xFFFF0000u);
                }
            // online softmax per row (row owners == fragment row distribution)
#pragma unroll
            for (int mt = 0; mt < 4; mt++)
#pragma unroll
                for (int rh = 0; rh < 2; rh++) {
                    int i0 = rh * 2;
                    float mp = fmaxf(fmaxf(s[mt][0][i0], s[mt][0][i0 + 1]),
                                     fmaxf(s[mt][1][i0], s[mt][1][i0 + 1]));
                    mp = fmaxf(mp, __shfl_xor_sync(0xffffffffu, mp, 1));
                    mp = fmaxf(mp, __shfl_xor_sync(0xffffffffu, mp, 2));
                    float mnew = fmaxf(mr[mt][rh], mp);
                    float corr = __expf(mr[mt][rh] - mnew);
                    mr[mt][rh] = mnew;
                    float ps = 0.0f;
#pragma unroll
                    for (int nt = 0; nt < 2; nt++)
#pragma unroll
                        for (int e2 = 0; e2 < 2; e2++) {
                            float p = __expf(s[mt][nt][i0 + e2] - mnew);
                            s[mt][nt][i0 + e2] = p;
                            ps += p;
                        }
                    lsm[mt][rh] = lsm[mt][rh] * corr + ps;
#pragma unroll
                    for (int nt = 0; nt < 2; nt++) {
                        o[mt][nt][i0]     *= corr;
                        o[mt][nt][i0 + 1] *= corr;
                    }
                }
            // V B-fragments
            unsigned vb[2][2][2];
#pragma unroll
            for (int t = 0; t < 2; t++)
#pragma unroll
                for (int nd = 0; nd < 2; nd++) {
                    const float* vp = qkv + (kb + t * 8 + q4) * QS + 256 + 16 * h + nd * 8 + g;
                    vb[t][nd][0] = __float_as_uint(vp[0]);
                    vb[t][nd][1] = __float_as_uint(vp[4 * QS]);
                }
            // P: C-frag -> A-frag via shuffle transpose; O += P V
#pragma unroll
            for (int mt = 0; mt < 4; mt++)
#pragma unroll
                for (int t = 0; t < 2; t++) {
                    unsigned p0 = f2tf(s[mt][t][0]), p1 = f2tf(s[mt][t][1]);
                    unsigned p2 = f2tf(s[mt][t][2]), p3 = f2tf(s[mt][t][3]);
                    unsigned v00 = __shfl_sync(0xffffffffu, p0, l0i);
                    unsigned v01 = __shfl_sync(0xffffffffu, p1, l0i);
                    unsigned v02 = __shfl_sync(0xffffffffu, p2, l0i);
                    unsigned v03 = __shfl_sync(0xffffffffu, p3, l0i);
                    unsigned v20 = __shfl_sync(0xffffffffu, p0, l2i);
                    unsigned v21 = __shfl_sync(0xffffffffu, p1, l2i);
                    unsigned v22 = __shfl_sync(0xffffffffu, p2, l2i);
                    unsigned v23 = __shfl_sync(0xffffffffu, p3, l2i);
                    unsigned a[4];
                    a[0] = hiSel ? v01 : v00;
                    a[1] = hiSel ? v03 : v02;
                    a[2] = hiSel ? v21 : v20;
                    a[3] = hiSel ? v23 : v22;
                    mma8(o[mt][0], a, vb[t][0][0], vb[t][0][1]);
                    mma8(o[mt][1], a, vb[t][1][0], vb[t][1][1]);
                }
        }
        // finalize 1/l
        float inv[4][2];
#pragma unroll
        for (int mt = 0; mt < 4; mt++)
#pragma unroll
            for (int rh = 0; rh < 2; rh++) {
                float l = lsm[mt][rh];
                l += __shfl_xor_sync(0xffffffffu, l, 1);
                l += __shfl_xor_sync(0xffffffffu, l, 2);
                inv[mt][rh] = 1.0f / l;
            }
        __syncthreads();                 // all warps done reading qkv
        float* outs = sm + OFF_QKV;      // reuse qkv region; stride 132
#pragma unroll
        for (int mt = 0; mt < 4; mt++)
#pragma unroll
            for (int nd = 0; nd < 2; nd++) {
                int row = mt * 16 + g, col = 16 * h + nd * 8 + 2 * q4;
                float2 v0, v1;
                v0.x = __uint_as_float(f2tf(o[mt][nd][0] * inv[mt][0]));
                v0.y = __uint_as_float(f2tf(o[mt][nd][1] * inv[mt][0]));
                v1.x = __uint_as_float(f2tf(o[mt][nd][2] * inv[mt][1]));
                v1.y = __uint_as_float(f2tf(o[mt][nd][3] * inv[mt][1]));
                *(float2*)(outs + row * 132 + col)       = v0;
                *(float2*)(outs + (row + 8) * 132 + col) = v1;
            }
    }

    // ---------------- phase 4: output projection via mma --------------------
    {
        float pacc[4][2][4];
#pragma unroll
        for (int mt = 0; mt < 4; mt++)
#pragma unroll
            for (int nt = 0; nt < 2; nt++)
#pragma unroll
                for (int i = 0; i < 4; i++) pacc[mt][nt][i] = 0.0f;

        const int nb0p = tr * 16;
        float* outs = sm + OFF_QKV;
        float* wp   = sm + OFF_WP;

        float4 pf[2];
        {
            const float4* src = (const float4*)g_proj_wt;
#pragma unroll
            for (int i = 0; i < 2; i++) pf[i] = src[i * 256 + tid];
        }
#pragma unroll 1
        for (int ch = 0; ch < 8; ch++) {
            __syncthreads();                       // outs ready / buffer free
#pragma unroll
            for (int i = 0; i < 2; i++) {          // STS chunk (16 k-rows, tf32)
                int idx = i * 256 + tid;           // 512 float4 = 16*128/4
                int r = idx >> 5, c4 = idx & 31;
                float4 w;
                w.x = __uint_as_float(f2tf(pf[i].x)); w.y = __uint_as_float(f2tf(pf[i].y));
                w.z = __uint_as_float(f2tf(pf[i].z)); w.w = __uint_as_float(f2tf(pf[i].w));
                *(float4*)(wp + r * 132 + c4 * 4) = w;
            }
            if (ch < 7) {
                const float4* src = (const float4*)(g_proj_wt + (ch + 1) * 16 * 128);
#pragma unroll
                for (int i = 0; i < 2; i++) pf[i] = src[i * 256 + tid];
            }
            __syncthreads();

#pragma unroll
            for (int ks = 0; ks < 2; ks++) {
                int kb = ks * 8;
                unsigned a[4][4];
#pragma unroll
                for (int mt = 0; mt < 4; mt++) {
                    const float* ap = outs + (mt * 16 + g) * 132 + ch * 16 + kb;
                    a[mt][0] = __float_as_uint(ap[q4]);
                    a[mt][1] = __float_as_uint(ap[8 * 132 + q4]);
                    a[mt][2] = __float_as_uint(ap[q4 + 4]);
                    a[mt][3] = __float_as_uint(ap[8 * 132 + q4 + 4]);
                }
#pragma unroll
                for (int nt = 0; nt < 2; nt++) {
                    int ncol = nb0p + nt * 8 + g;
                    unsigned b0 = __float_as_uint(wp[(kb + q4) * 132 + ncol]);
                    unsigned b1 = __float_as_uint(wp[(kb + q4 + 4) * 132 + ncol]);
#pragma unroll
                    for (int mt = 0; mt < 4; mt++) mma8(pacc[mt][nt], a[mt], b0, b1);
                }
            }
        }
        // epilogue: global writes + bias
        float* og = out + row0 * 128;
#pragma unroll
        for (int mt = 0; mt < 4; mt++)
#pragma unroll
            for (int nt = 0; nt < 2; nt++) {
                int row = mt * 16 + g, col = nb0p + nt * 8 + 2 * q4;
                float bx = __ldg(proj_b + col), by = __ldg(proj_b + col + 1);
                *(float2*)(og + row * 128 + col) =
                    make_float2(pacc[mt][nt][0] + bx, pacc[mt][nt][1] + by);
                *(float2*)(og + (row + 8) * 128 + col) =
                    make_float2(pacc[mt][nt][2] + bx, pacc[mt][nt][3] + by);
            }
    }
}

extern "C" void kernel_launch(void* const* d_in, const int* in_sizes, int n_in,
                              void* d_out, int out_size)
{
    (void)in_sizes; (void)n_in; (void)out_size;
    const float* x      = (const float*)d_in[0];
    const int*   am     = (const int*)  d_in[1];
    const float* ef     = (const float*)d_in[2];
    const float* qkv_w  = (const float*)d_in[3];
    const float* qkv_b  = (const float*)d_in[4];
    const float* proj_w = (const float*)d_in[5];
    const float* proj_b = (const float*)d_in[6];
    const float* eg_w1  = (const float*)d_in[7];
    const float* eg_b1  = (const float*)d_in[8];
    const float* eg_w2  = (const float*)d_in[9];
    const float* eg_b2  = (const float*)d_in[10];
    float* out = (float*)d_out;

    k_transpose_w<<<256, 256>>>(qkv_w, proj_w);

    cudaFuncSetAttribute(fused_attn,
                         cudaFuncAttributeMaxDynamicSharedMemorySize, SMEM_BYTES);
    fused_attn<<<1024, 256, SMEM_BYTES>>>(x, am, ef, qkv_b, proj_b,
                                          eg_w1, eg_b1, eg_w2, eg_b2, out);
}